// round 13
// baseline (speedup 1.0000x reference)
#include <cuda_runtime.h>
#include <cuda_fp16.h>
#include <cstdint>

// ---------------- problem dims ----------------
#define MROWS 65536     // T*B
#define IIK   512       // K
#define G4    2048      // 4*H
#define BB    64        // batch
#define HHH   512       // H

// ---------------- tiling ----------------
#define TM   128        // M rows per CTA
#define TNH  32         // hy cols per CTA -> 128 gate cols
#define KC   32         // K chunk
#define NIT  16         // 512/32
#define NPAIR 8
#define NSTAGE 6

// stage: A (128 rows x 64B, XOR-swizzled granules) + B (same)
#define ROWSTR 64
#define A_BYTES (128 * ROWSTR)        // 8192
#define B_OFF   A_BYTES
#define STG     (2 * A_BYTES)         // 16384
#define SMEMT   (NSTAGE * STG)        // 98304; epilogue reuses 128x132 f32 (67584)

// ---------------- device scratch (no runtime alloc) ----------------
__device__ __align__(16) __half g_A0[(size_t)MROWS * IIK];
__device__ __align__(16) __half g_A1[(size_t)MROWS * IIK];
__device__ __align__(16) __half g_W[2][G4 * IIK];
__device__ float g_hh[2][BB][G4];

// ---------------- asm helpers (plain sm_80/90 PTX only) ----------------
__device__ __forceinline__ uint32_t smem_to_u32(const void* p) {
    uint32_t a;
    asm("{ .reg .u64 t; cvta.to.shared.u64 t, %1; cvt.u32.u64 %0, t; }"
        : "=r"(a) : "l"(p));
    return a;
}
#define CP_ASYNC16(s, g) \
    asm volatile("cp.async.cg.shared.global [%0], [%1], 16;" :: "r"(s), "l"(g))
#define CP_COMMIT() asm volatile("cp.async.commit_group;" ::: "memory")
#define CP_WAIT2()  asm volatile("cp.async.wait_group 2;" ::: "memory")
#define CP_WAIT0()  asm volatile("cp.async.wait_group 0;" ::: "memory")

#define LDSM4(r, addr) \
    asm volatile("ldmatrix.sync.aligned.m8n8.x4.shared.b16 {%0,%1,%2,%3}, [%4];" \
        : "=r"((r)[0]), "=r"((r)[1]), "=r"((r)[2]), "=r"((r)[3]) : "r"(addr))

__device__ __forceinline__ void mma_f16(float* c, const unsigned* a, const unsigned* b) {
    asm volatile(
        "mma.sync.aligned.m16n8k16.row.col.f32.f16.f16.f32 "
        "{%0,%1,%2,%3}, {%4,%5,%6,%7}, {%8,%9}, {%0,%1,%2,%3};"
        : "+f"(c[0]), "+f"(c[1]), "+f"(c[2]), "+f"(c[3])
        : "r"(a[0]), "r"(a[1]), "r"(a[2]), "r"(a[3]), "r"(b[0]), "r"(b[1]));
}

// ---------------- activations ----------------
__device__ __forceinline__ float sigf(float x) {
    return __fdividef(1.0f, 1.0f + __expf(-x));
}
__device__ __forceinline__ float tanhf_(float x) {
    return 2.0f * sigf(2.0f * x) - 1.0f;
}

// ---------------------------------------------------------------------------
// converters: x -> fp16, weights -> fp16
// ---------------------------------------------------------------------------
__global__ void cvt_x(const float* __restrict__ src, int n4) {
    int i = blockIdx.x * blockDim.x + threadIdx.x;
    if (i >= n4) return;
    float4 v = ((const float4*)src)[i];
    ((__half2*)g_A0)[2*i]   = __half2(__float2half(v.x), __float2half(v.y));
    ((__half2*)g_A0)[2*i+1] = __half2(__float2half(v.z), __float2half(v.w));
}

__global__ void cvt_w(const float* __restrict__ w0, const float* __restrict__ w1, int n4) {
    int i = blockIdx.x * blockDim.x + threadIdx.x;
    if (i >= n4) return;
    float4 a = ((const float4*)w0)[i];
    float4 b = ((const float4*)w1)[i];
    ((__half2*)g_W[0])[2*i]   = __half2(__float2half(a.x), __float2half(a.y));
    ((__half2*)g_W[0])[2*i+1] = __half2(__float2half(a.z), __float2half(a.w));
    ((__half2*)g_W[1])[2*i]   = __half2(__float2half(b.x), __float2half(b.y));
    ((__half2*)g_W[1])[2*i+1] = __half2(__float2half(b.z), __float2half(b.w));
}

// ---------------------------------------------------------------------------
// hh[l][b][g] = h0[l][b] . w_hh[g] + b_ih[g] + b_hh[g]   (fp32 tiled GEMM)
// ---------------------------------------------------------------------------
__global__ void __launch_bounds__(256)
hh_kernel(const float* __restrict__ h0,
          const float* __restrict__ w_hh_0, const float* __restrict__ w_hh_1,
          const float* __restrict__ b_ih_0, const float* __restrict__ b_hh_0,
          const float* __restrict__ b_ih_1, const float* __restrict__ b_hh_1) {
    const int layer = blockIdx.y;
    const int g0 = blockIdx.x * 64;
    const float* __restrict__ w  = layer ? w_hh_1 : w_hh_0;
    const float* __restrict__ bi = layer ? b_ih_1 : b_ih_0;
    const float* __restrict__ bh = layer ? b_hh_1 : b_hh_0;

    __shared__ __align__(16) float As[32][68];
    __shared__ __align__(16) float Bs[32][68];

    const int tid = threadIdx.x;
    const int tx = tid & 15;
    const int ty = tid >> 4;
    const int lr  = tid >> 3;
    const int lk4 = tid & 7;

    float acc[4][4];
#pragma unroll
    for (int i = 0; i < 4; i++)
#pragma unroll
        for (int j = 0; j < 4; j++) acc[i][j] = 0.0f;

    for (int k0 = 0; k0 < IIK; k0 += 32) {
#pragma unroll
        for (int rep = 0; rep < 2; ++rep) {
            const int row = lr + rep * 32;
            float4 av = *(const float4*)(h0 + ((size_t)layer * BB + row) * IIK + k0 + lk4 * 4);
            As[lk4 * 4 + 0][row] = av.x;
            As[lk4 * 4 + 1][row] = av.y;
            As[lk4 * 4 + 2][row] = av.z;
            As[lk4 * 4 + 3][row] = av.w;
            float4 bv = *(const float4*)(w + (size_t)(g0 + row) * IIK + k0 + lk4 * 4);
            Bs[lk4 * 4 + 0][row] = bv.x;
            Bs[lk4 * 4 + 1][row] = bv.y;
            Bs[lk4 * 4 + 2][row] = bv.z;
            Bs[lk4 * 4 + 3][row] = bv.w;
        }
        __syncthreads();
#pragma unroll
        for (int k = 0; k < 32; ++k) {
            float a_[4], b_[4];
#pragma unroll
            for (int i = 0; i < 4; i++) a_[i] = As[k][ty * 4 + i];
#pragma unroll
            for (int j = 0; j < 4; j++) b_[j] = Bs[k][tx * 4 + j];
#pragma unroll
            for (int i = 0; i < 4; i++)
#pragma unroll
                for (int j = 0; j < 4; j++) acc[i][j] = fmaf(a_[i], b_[j], acc[i][j]);
        }
        __syncthreads();
    }
#pragma unroll
    for (int i = 0; i < 4; i++) {
        const int b = ty * 4 + i;
#pragma unroll
        for (int j = 0; j < 4; j++) {
            const int g = g0 + tx * 4 + j;
            g_hh[layer][b][g] = acc[i][j] + bi[g] + bh[g];
        }
    }
}

// ---------------------------------------------------------------------------
// Main HMMA LSTM layer kernel.  grid (16, 512), 256 threads, 2 CTAs/SM.
// Warp tile 32x64; KC=32; 6-stage cp.async (XOR-swizzled 64B rows);
// prologue 4 chunks; ONE sync + wait_group(2) per 2 chunks (2-pair slack).
// Swizzle: granule g at row r stored at granule slot (g + (r>>1)) & 3.
// Gate-interleaved B rows: smem B row n <-> w_ih row (n%4)*512 + n0h + n/4.
// ---------------------------------------------------------------------------
__global__ void __launch_bounds__(256, 2)
lstm_mma_kernel(const float* __restrict__ c0,
                float* __restrict__ res,
                float* __restrict__ lh,
                float* __restrict__ lc,
                int layer) {
    extern __shared__ __align__(16) char sm[];
    const uint32_t smem_u32 = smem_to_u32(sm);
    const int tid  = threadIdx.x;
    const int wid  = tid >> 5;
    const int lane = tid & 31;
    const int n0h  = blockIdx.x * TNH;
    const int m0   = blockIdx.y * TM;

    const __half* __restrict__ Ax = layer ? g_A1 : g_A0;
    const __half* __restrict__ Wp = g_W[layer];
    const float* __restrict__ hh_l = &g_hh[layer][0][0];
    const float* __restrict__ c0_l = c0 + (size_t)layer * BB * HHH;
    float* __restrict__ lasth = lh + (size_t)layer * BB * HHH;
    float* __restrict__ lastc = lc + (size_t)layer * BB * HHH;

    // ---- loader: per-thread running pointers (4 cp.async per stage) ----
    const int lrow = tid >> 2;           // 0..63 (rows lrow and lrow+64)
    const int lgc  = tid & 3;            // source 16B granule along k
    const __half* pA0 = Ax + (size_t)(m0 + lrow) * IIK + lgc * 8;
    const int wrow0 = (lrow & 3) * 512 + n0h + (lrow >> 2);   // wrow1 = wrow0+16
    const __half* pB0 = Wp + (size_t)wrow0 * IIK + lgc * 8;
    // swizzled dest: slot (lgc + (lrow>>1)) & 3; rows r and r+64 share the slot
    const uint32_t soff = lrow * ROWSTR + (((lgc + (lrow >> 1)) & 3) << 4);
    int lstage = 0;

#define LOAD_STAGE()                                                           \
    do {                                                                       \
        const uint32_t _sb = smem_u32 + lstage * STG;                          \
        CP_ASYNC16(_sb + soff,                pA0);                            \
        CP_ASYNC16(_sb + soff + 4096,         pA0 + (size_t)64 * IIK);         \
        CP_ASYNC16(_sb + B_OFF + soff,        pB0);                            \
        CP_ASYNC16(_sb + B_OFF + soff + 4096, pB0 + (size_t)16 * IIK);         \
        CP_COMMIT();                                                           \
        pA0 += KC; pB0 += KC;                                                  \
        lstage = (lstage + 1 == NSTAGE) ? 0 : lstage + 1;                      \
    } while (0)

    // ---- ldmatrix invariants: warp grid 4 (wm, 32 rows) x 2 (wn, 64 cols) ----
    const int wm = wid & 3;
    const int wn = wid >> 2;
    // A: row = wm*32 + mt*16 + (lane&15); (row>>1)&3 invariant in mt
    const int aRow = wm * 32 + (lane & 15);
    const int gA = ((lane >> 4) & 1) + ((aRow >> 1) & 3);
    const uint32_t aBase = (uint32_t)aRow * ROWSTR;
    const uint32_t swA[2] = { (uint32_t)((gA & 3) << 4),
                              (uint32_t)(((gA + 2) & 3) << 4) };
    // B: row = wn*64 + p*16 + ((lane>>4)&1)*8 + (lane&7); (row>>1)&3 inv. in p
    const int bRow = wn * 64 + ((lane >> 4) & 1) * 8 + (lane & 7);
    const int gB = ((lane >> 3) & 1) + ((bRow >> 1) & 3);
    const uint32_t bBase = B_OFF + (uint32_t)bRow * ROWSTR;
    const uint32_t swB[2] = { (uint32_t)((gB & 3) << 4),
                              (uint32_t)(((gB + 2) & 3) << 4) };

    float acc[2][8][4];
#pragma unroll
    for (int mt = 0; mt < 2; ++mt)
#pragma unroll
        for (int nb = 0; nb < 8; ++nb)
#pragma unroll
            for (int q = 0; q < 4; ++q) acc[mt][nb][q] = 0.0f;

#define COMPUTE_CHUNK(SBASE)                                                   \
    do {                                                                       \
        const uint32_t _cb = (SBASE);                                          \
        _Pragma("unroll")                                                      \
        for (int ks = 0; ks < 2; ++ks) {                                       \
            unsigned ah[2][4];                                                 \
            _Pragma("unroll")                                                  \
            for (int mt = 0; mt < 2; ++mt)                                     \
                LDSM4(ah[mt], _cb + aBase + (uint32_t)(mt * 1024) + swA[ks]);  \
            unsigned bh[4][4];                                                 \
            _Pragma("unroll")                                                  \
            for (int p = 0; p < 4; ++p)                                        \
                LDSM4(bh[p], _cb + bBase + (uint32_t)(p * 1024) + swB[ks]);    \
            _Pragma("unroll")                                                  \
            for (int mt = 0; mt < 2; ++mt)                                     \
                _Pragma("unroll")                                              \
                for (int p = 0; p < 4; ++p) {                                  \
                    mma_f16(acc[mt][2*p],   ah[mt], &bh[p][0]);                \
                    mma_f16(acc[mt][2*p+1], ah[mt], &bh[p][2]);                \
                }                                                              \
        }                                                                      \
    } while (0)

    LOAD_STAGE();   // chunk 0
    LOAD_STAGE();   // chunk 1
    LOAD_STAGE();   // chunk 2
    LOAD_STAGE();   // chunk 3

    for (int j = 0; j < NPAIR; ++j) {
        if (j + 1 < NPAIR) CP_WAIT2(); else CP_WAIT0();
        __syncthreads();          // pair barrier: data visibility + stage-reuse guard

        // stages of chunks 2j+4, 2j+5 were consumed in pair j-1 -> safe now
        if (2 * j + 4 < NIT) LOAD_STAGE();
        if (2 * j + 5 < NIT) LOAD_STAGE();

        const int s0 = (2 * j) % NSTAGE;
        const int s1 = (2 * j + 1) % NSTAGE;
        COMPUTE_CHUNK(smem_u32 + s0 * STG);
        COMPUTE_CHUNK(smem_u32 + s1 * STG);   // no barrier between the two
    }
    __syncthreads();              // all LDSM done before smem reuse as Gs

    // ---- epilogue: dump gate tile (128 x 128 f32, stride 132) into smem ----
    float* Gs = (float*)sm;
#pragma unroll
    for (int mt = 0; mt < 2; ++mt) {
        const int r0 = wm * 32 + mt * 16 + (lane >> 2);
#pragma unroll
        for (int nb = 0; nb < 8; ++nb) {
            const int cb = wn * 64 + nb * 8 + (lane & 3) * 2;
            Gs[r0 * 132 + cb]           = acc[mt][nb][0];
            Gs[r0 * 132 + cb + 1]       = acc[mt][nb][1];
            Gs[(r0 + 8) * 132 + cb]     = acc[mt][nb][2];
            Gs[(r0 + 8) * 132 + cb + 1] = acc[mt][nb][3];
        }
    }
    __syncthreads();

    // ---- fused LSTM pointwise: 128 rows x 16 col-pairs per CTA ----
    for (int e = tid; e < TM * (TNH / 2); e += 256) {
        const int row = e >> 4;
        const int c2  = e & 15;
        const int m   = m0 + row;
        const int b   = m & (BB - 1);
        const int nh  = n0h + c2 * 2;
        const float* hhb = hh_l + (size_t)b * G4;
        float hy2[2], cy2[2];
#pragma unroll
        for (int u = 0; u < 2; ++u) {
            const int col = c2 * 2 + u;
            float ig = Gs[row * 132 + col * 4 + 0] + hhb[nh + u];
            float fg = Gs[row * 132 + col * 4 + 1] + hhb[512 + nh + u];
            float gg = Gs[row * 132 + col * 4 + 2] + hhb[1024 + nh + u];
            float og = Gs[row * 132 + col * 4 + 3] + hhb[1536 + nh + u];
            float cy = sigf(fg) * c0_l[(size_t)b * HHH + nh + u] + sigf(ig) * tanhf_(gg);
            cy2[u] = cy;
            hy2[u] = sigf(og) * tanhf_(cy);
        }
        if (layer == 0) {
            *(__half2*)(g_A1 + (size_t)m * HHH + nh) =
                __half2(__float2half(hy2[0]), __float2half(hy2[1]));
        } else {
            *(float2*)(res + (size_t)m * HHH + nh) = make_float2(hy2[0], hy2[1]);
        }
        if (m >= MROWS - BB) {
            *(float2*)(lasth + (size_t)b * HHH + nh) = make_float2(hy2[0], hy2[1]);
            *(float2*)(lastc + (size_t)b * HHH + nh) = make_float2(cy2[0], cy2[1]);
        }
    }
}

// ---------------------------------------------------------------------------
extern "C" void kernel_launch(void* const* d_in, const int* in_sizes, int n_in,
                              void* d_out, int out_size) {
    const float* x      = (const float*)d_in[0];
    const float* h0     = (const float*)d_in[1];
    const float* c0     = (const float*)d_in[2];
    const float* w_ih_0 = (const float*)d_in[3];
    const float* w_hh_0 = (const float*)d_in[4];
    const float* b_ih_0 = (const float*)d_in[5];
    const float* b_hh_0 = (const float*)d_in[6];
    const float* w_ih_1 = (const float*)d_in[7];
    const float* w_hh_1 = (const float*)d_in[8];
    const float* b_ih_1 = (const float*)d_in[9];
    const float* b_hh_1 = (const float*)d_in[10];
    (void)in_sizes; (void)n_in; (void)out_size;

    float* out = (float*)d_out;
    float* res = out;                                  // [65536, 512]
    float* lh  = out + (size_t)MROWS * HHH;            // [2, 64, 512]
    float* lc  = lh + 2 * BB * HHH;                    // [2, 64, 512]

    cudaFuncSetAttribute(lstm_mma_kernel,
                         cudaFuncAttributeMaxDynamicSharedMemorySize, SMEMT);

    // precision pre-pass
    cvt_x<<<(MROWS * IIK / 4 + 255) / 256, 256>>>(x, MROWS * IIK / 4);
    cvt_w<<<(G4 * IIK / 4 + 255) / 256, 256>>>(w_ih_0, w_ih_1, G4 * IIK / 4);

    // hh precompute (tiled GEMM, both layers in one launch)
    dim3 hgrid(G4 / 64, 2);
    hh_kernel<<<hgrid, 256>>>(h0, w_hh_0, w_hh_1, b_ih_0, b_hh_0, b_ih_1, b_hh_1);

    // HMMA layers
    dim3 ggrid(HHH / TNH, MROWS / TM);   // (16, 512)
    lstm_mma_kernel<<<ggrid, 256, SMEMT>>>(c0, res, lh, lc, 0);
    lstm_mma_kernel<<<ggrid, 256, SMEMT>>>(c0, res, lh, lc, 1);
}

// round 15
// speedup vs baseline: 1.0710x; 1.0710x over previous
#include <cuda_runtime.h>
#include <cuda_fp16.h>
#include <cstdint>

// ---------------- problem dims ----------------
#define MROWS 65536     // T*B
#define IIK   512       // K
#define G4    2048      // 4*H
#define BB    64        // batch
#define HHH   512       // H

// ---------------- tiling ----------------
#define TM   128        // M rows per CTA
#define TNH  32         // hy cols per CTA -> 128 gate cols
#define KC   32         // K chunk
#define NIT  16         // 512/32
#define NPAIR 8
#define NSTAGE 5

// stage: A (128 rows x 80B) + B (128 rows x 80B)
#define ROWSTR 80
#define A_BYTES (128 * ROWSTR)        // 10240
#define B_OFF   A_BYTES
#define STG     (2 * A_BYTES)         // 20480
#define SMEMT   (NSTAGE * STG)        // 102400; epilogue reuses 128x132 f32 (67584)

// ---------------- device scratch (no runtime alloc) ----------------
__device__ __align__(16) __half g_A0[(size_t)MROWS * IIK];
__device__ __align__(16) __half g_A1[(size_t)MROWS * IIK];
__device__ __align__(16) __half g_W[2][G4 * IIK];
__device__ float g_hh[2][BB][G4];

// ---------------- asm helpers (plain sm_80/90 PTX only) ----------------
__device__ __forceinline__ uint32_t smem_to_u32(const void* p) {
    uint32_t a;
    asm("{ .reg .u64 t; cvta.to.shared.u64 t, %1; cvt.u32.u64 %0, t; }"
        : "=r"(a) : "l"(p));
    return a;
}
#define CP_ASYNC16(s, g) \
    asm volatile("cp.async.cg.shared.global [%0], [%1], 16;" :: "r"(s), "l"(g))
#define CP_COMMIT() asm volatile("cp.async.commit_group;" ::: "memory")
#define CP_WAIT1()  asm volatile("cp.async.wait_group 1;" ::: "memory")
#define CP_WAIT0()  asm volatile("cp.async.wait_group 0;" ::: "memory")

#define LDSM4(r, addr) \
    asm volatile("ldmatrix.sync.aligned.m8n8.x4.shared.b16 {%0,%1,%2,%3}, [%4];" \
        : "=r"((r)[0]), "=r"((r)[1]), "=r"((r)[2]), "=r"((r)[3]) : "r"(addr))

__device__ __forceinline__ void mma_f16(float* c, const unsigned* a, const unsigned* b) {
    asm volatile(
        "mma.sync.aligned.m16n8k16.row.col.f32.f16.f16.f32 "
        "{%0,%1,%2,%3}, {%4,%5,%6,%7}, {%8,%9}, {%0,%1,%2,%3};"
        : "+f"(c[0]), "+f"(c[1]), "+f"(c[2]), "+f"(c[3])
        : "r"(a[0]), "r"(a[1]), "r"(a[2]), "r"(a[3]), "r"(b[0]), "r"(b[1]));
}

// ---------------- activations (tanh.approx: 1 MUFU each) ----------------
__device__ __forceinline__ float tanh_ap(float x) {
    float r;
    asm("tanh.approx.f32 %0, %1;" : "=f"(r) : "f"(x));
    return r;
}
__device__ __forceinline__ float sigf(float x) {
    return fmaf(tanh_ap(0.5f * x), 0.5f, 0.5f);
}

// ---------------------------------------------------------------------------
// fused converter: x -> fp16 (g_A0) and both weight matrices -> fp16 (g_W)
// grid.x covers max(n4x, n4w); blocks with idx < n4w also convert weights.
// ---------------------------------------------------------------------------
__global__ void cvt_all(const float* __restrict__ x,
                        const float* __restrict__ w0,
                        const float* __restrict__ w1,
                        int n4x, int n4w) {
    int i = blockIdx.x * blockDim.x + threadIdx.x;
    if (i < n4x) {
        float4 v = ((const float4*)x)[i];
        ((__half2*)g_A0)[2*i]   = __half2(__float2half(v.x), __float2half(v.y));
        ((__half2*)g_A0)[2*i+1] = __half2(__float2half(v.z), __float2half(v.w));
    }
    if (i < n4w) {
        float4 a = ((const float4*)w0)[i];
        float4 b = ((const float4*)w1)[i];
        ((__half2*)g_W[0])[2*i]   = __half2(__float2half(a.x), __float2half(a.y));
        ((__half2*)g_W[0])[2*i+1] = __half2(__float2half(a.z), __float2half(a.w));
        ((__half2*)g_W[1])[2*i]   = __half2(__float2half(b.x), __float2half(b.y));
        ((__half2*)g_W[1])[2*i+1] = __half2(__float2half(b.z), __float2half(b.w));
    }
}

// ---------------------------------------------------------------------------
// hh[l][b][g] = h0[l][b] . w_hh[g] + b_ih[g] + b_hh[g]   (fp32 tiled GEMM)
// ---------------------------------------------------------------------------
__global__ void __launch_bounds__(256)
hh_kernel(const float* __restrict__ h0,
          const float* __restrict__ w_hh_0, const float* __restrict__ w_hh_1,
          const float* __restrict__ b_ih_0, const float* __restrict__ b_hh_0,
          const float* __restrict__ b_ih_1, const float* __restrict__ b_hh_1) {
    const int layer = blockIdx.y;
    const int g0 = blockIdx.x * 64;
    const float* __restrict__ w  = layer ? w_hh_1 : w_hh_0;
    const float* __restrict__ bi = layer ? b_ih_1 : b_ih_0;
    const float* __restrict__ bh = layer ? b_hh_1 : b_hh_0;

    __shared__ __align__(16) float As[32][68];
    __shared__ __align__(16) float Bs[32][68];

    const int tid = threadIdx.x;
    const int tx = tid & 15;
    const int ty = tid >> 4;
    const int lr  = tid >> 3;
    const int lk4 = tid & 7;

    float acc[4][4];
#pragma unroll
    for (int i = 0; i < 4; i++)
#pragma unroll
        for (int j = 0; j < 4; j++) acc[i][j] = 0.0f;

    for (int k0 = 0; k0 < IIK; k0 += 32) {
#pragma unroll
        for (int rep = 0; rep < 2; ++rep) {
            const int row = lr + rep * 32;
            float4 av = *(const float4*)(h0 + ((size_t)layer * BB + row) * IIK + k0 + lk4 * 4);
            As[lk4 * 4 + 0][row] = av.x;
            As[lk4 * 4 + 1][row] = av.y;
            As[lk4 * 4 + 2][row] = av.z;
            As[lk4 * 4 + 3][row] = av.w;
            float4 bv = *(const float4*)(w + (size_t)(g0 + row) * IIK + k0 + lk4 * 4);
            Bs[lk4 * 4 + 0][row] = bv.x;
            Bs[lk4 * 4 + 1][row] = bv.y;
            Bs[lk4 * 4 + 2][row] = bv.z;
            Bs[lk4 * 4 + 3][row] = bv.w;
        }
        __syncthreads();
#pragma unroll
        for (int k = 0; k < 32; ++k) {
            float a_[4], b_[4];
#pragma unroll
            for (int i = 0; i < 4; i++) a_[i] = As[k][ty * 4 + i];
#pragma unroll
            for (int j = 0; j < 4; j++) b_[j] = Bs[k][tx * 4 + j];
#pragma unroll
            for (int i = 0; i < 4; i++)
#pragma unroll
                for (int j = 0; j < 4; j++) acc[i][j] = fmaf(a_[i], b_[j], acc[i][j]);
        }
        __syncthreads();
    }
#pragma unroll
    for (int i = 0; i < 4; i++) {
        const int b = ty * 4 + i;
#pragma unroll
        for (int j = 0; j < 4; j++) {
            const int g = g0 + tx * 4 + j;
            g_hh[layer][b][g] = acc[i][j] + bi[g] + bh[g];
        }
    }
}

// ---------------------------------------------------------------------------
// Main HMMA LSTM layer kernel.  grid (16, 512), 256 threads, 2 CTAs/SM.
// Warp tile 32x64; KC=32; 5-stage cp.async; ONE sync + ONE wait per 2 chunks.
// (Exact R9 mainloop structure — empirically the best found.)
// Gate-interleaved B rows: smem B row n <-> w_ih row (n%4)*512 + n0h + n/4.
// ---------------------------------------------------------------------------
__global__ void __launch_bounds__(256, 2)
lstm_mma_kernel(const float* __restrict__ c0,
                float* __restrict__ res,
                float* __restrict__ lh,
                float* __restrict__ lc,
                int layer) {
    extern __shared__ __align__(16) char sm[];
    const uint32_t smem_u32 = smem_to_u32(sm);
    const int tid  = threadIdx.x;
    const int wid  = tid >> 5;
    const int lane = tid & 31;
    const int n0h  = blockIdx.x * TNH;
    const int m0   = blockIdx.y * TM;

    const __half* __restrict__ Ax = layer ? g_A1 : g_A0;
    const __half* __restrict__ Wp = g_W[layer];
    const float* __restrict__ hh_l = &g_hh[layer][0][0];
    const float* __restrict__ c0_l = c0 + (size_t)layer * BB * HHH;
    float* __restrict__ lasth = lh + (size_t)layer * BB * HHH;
    float* __restrict__ lastc = lc + (size_t)layer * BB * HHH;

    // ---- loader: per-thread running pointers (4 cp.async per stage) ----
    const int lrow = tid >> 2;           // 0..63 (rows lrow and lrow+64)
    const int lgc  = tid & 3;            // 16B granule along k
    const __half* pA0 = Ax + (size_t)(m0 + lrow) * IIK + lgc * 8;
    const __half* pA1 = pA0 + (size_t)64 * IIK;
    const int wrow0 = (lrow & 3) * 512 + n0h + (lrow >> 2);
    const int wrow1 = ((lrow + 64) & 3) * 512 + n0h + ((lrow + 64) >> 2);
    const __half* pB0 = Wp + (size_t)wrow0 * IIK + lgc * 8;
    const __half* pB1 = Wp + (size_t)wrow1 * IIK + lgc * 8;
    const uint32_t aoff0 = lrow * ROWSTR + lgc * 16;
    const uint32_t aoff1 = aoff0 + 64 * ROWSTR;
    int lstage = 0;

#define LOAD_STAGE()                                                           \
    do {                                                                       \
        const uint32_t _sb = smem_u32 + lstage * STG;                          \
        CP_ASYNC16(_sb + aoff0,         pA0);                                  \
        CP_ASYNC16(_sb + aoff1,         pA1);                                  \
        CP_ASYNC16(_sb + B_OFF + aoff0, pB0);                                  \
        CP_ASYNC16(_sb + B_OFF + aoff1, pB1);                                  \
        CP_COMMIT();                                                           \
        pA0 += KC; pA1 += KC; pB0 += KC; pB1 += KC;                            \
        lstage = (lstage + 1 == NSTAGE) ? 0 : lstage + 1;                      \
    } while (0)

    // ---- ldmatrix invariants: warp grid 4 (wm, 32 rows) x 2 (wn, 64 cols) ----
    const int wm = wid & 3;
    const int wn = wid >> 2;
    const uint32_t aBase = (uint32_t)(wm * 32) * ROWSTR
                         + (uint32_t)(lane & 15) * ROWSTR
                         + (uint32_t)((lane >> 4) & 1) * 16;
    const uint32_t bBase = B_OFF + (uint32_t)(wn * 64) * ROWSTR
                         + (uint32_t)(((lane >> 4) & 1) * 8 + (lane & 7)) * ROWSTR
                         + (uint32_t)((lane >> 3) & 1) * 16;

    float acc[2][8][4];
#pragma unroll
    for (int mt = 0; mt < 2; ++mt)
#pragma unroll
        for (int nb = 0; nb < 8; ++nb)
#pragma unroll
            for (int q = 0; q < 4; ++q) acc[mt][nb][q] = 0.0f;

#define COMPUTE_CHUNK(SBASE)                                                   \
    do {                                                                       \
        const uint32_t _cb = (SBASE);                                          \
        _Pragma("unroll")                                                      \
        for (int ks = 0; ks < 2; ++ks) {                                       \
            unsigned ah[2][4];                                                 \
            _Pragma("unroll")                                                  \
            for (int mt = 0; mt < 2; ++mt)                                     \
                LDSM4(ah[mt], _cb + aBase + (uint32_t)(mt * 16) * ROWSTR + ks * 32); \
            unsigned bh[4][4];                                                 \
            _Pragma("unroll")                                                  \
            for (int p = 0; p < 4; ++p)                                        \
                LDSM4(bh[p], _cb + bBase + (uint32_t)(p * 16) * ROWSTR + ks * 32);   \
            _Pragma("unroll")                                                  \
            for (int mt = 0; mt < 2; ++mt)                                     \
                _Pragma("unroll")                                              \
                for (int p = 0; p < 4; ++p) {                                  \
                    mma_f16(acc[mt][2*p],   ah[mt], &bh[p][0]);                \
                    mma_f16(acc[mt][2*p+1], ah[mt], &bh[p][2]);                \
                }                                                              \
        }                                                                      \
    } while (0)

    LOAD_STAGE();   // stage 0
    LOAD_STAGE();   // stage 1
    LOAD_STAGE();   // stage 2

    for (int j = 0; j < NPAIR; ++j) {
        if (j + 1 < NPAIR) CP_WAIT1(); else CP_WAIT0();
        __syncthreads();          // pair barrier: data visibility + stage-reuse guard
        if (2 * j + 3 < NIT) LOAD_STAGE();
        if (2 * j + 4 < NIT) LOAD_STAGE();

        const int s0 = (2 * j) % NSTAGE;
        const int s1 = (2 * j + 1) % NSTAGE;
        COMPUTE_CHUNK(smem_u32 + s0 * STG);
        COMPUTE_CHUNK(smem_u32 + s1 * STG);   // no barrier between the two
    }
    __syncthreads();              // all LDSM done before smem reuse as Gs

    // ---- epilogue: dump gate tile (128 x 128 f32, stride 132) into smem ----
    float* Gs = (float*)sm;
#pragma unroll
    for (int mt = 0; mt < 2; ++mt) {
        const int r0 = wm * 32 + mt * 16 + (lane >> 2);
#pragma unroll
        for (int nb = 0; nb < 8; ++nb) {
            const int cb = wn * 64 + nb * 8 + (lane & 3) * 2;
            Gs[r0 * 132 + cb]           = acc[mt][nb][0];
            Gs[r0 * 132 + cb + 1]       = acc[mt][nb][1];
            Gs[(r0 + 8) * 132 + cb]     = acc[mt][nb][2];
            Gs[(r0 + 8) * 132 + cb + 1] = acc[mt][nb][3];
        }
    }
    __syncthreads();

    // ---- fused LSTM pointwise: 128 rows x 16 col-pairs per CTA ----
    // 4 gates of one hy col contiguous in Gs -> one float4 LDS each.
    for (int e = tid; e < TM * (TNH / 2); e += 256) {
        const int row = e >> 4;
        const int c2  = e & 15;
        const int m   = m0 + row;
        const int b   = m & (BB - 1);
        const int nh  = n0h + c2 * 2;
        const float* hhb = hh_l + (size_t)b * G4;
        float hy2[2], cy2[2];
#pragma unroll
        for (int u = 0; u < 2; ++u) {
            const int col = c2 * 2 + u;
            float4 gv4 = *(const float4*)&Gs[row * 132 + col * 4];
            float ig = gv4.x + hhb[nh + u];
            float fg = gv4.y + hhb[512 + nh + u];
            float gg = gv4.z + hhb[1024 + nh + u];
            float og = gv4.w + hhb[1536 + nh + u];
            float cy = sigf(fg) * c0_l[(size_t)b * HHH + nh + u] + sigf(ig) * tanh_ap(gg);
            cy2[u] = cy;
            hy2[u] = sigf(og) * tanh_ap(cy);
        }
        if (layer == 0) {
            *(__half2*)(g_A1 + (size_t)m * HHH + nh) =
                __half2(__float2half(hy2[0]), __float2half(hy2[1]));
        } else {
            *(float2*)(res + (size_t)m * HHH + nh) = make_float2(hy2[0], hy2[1]);
        }
        if (m >= MROWS - BB) {
            *(float2*)(lasth + (size_t)b * HHH + nh) = make_float2(hy2[0], hy2[1]);
            *(float2*)(lastc + (size_t)b * HHH + nh) = make_float2(cy2[0], cy2[1]);
        }
    }
}

// ---------------------------------------------------------------------------
extern "C" void kernel_launch(void* const* d_in, const int* in_sizes, int n_in,
                              void* d_out, int out_size) {
    const float* x      = (const float*)d_in[0];
    const float* h0     = (const float*)d_in[1];
    const float* c0     = (const float*)d_in[2];
    const float* w_ih_0 = (const float*)d_in[3];
    const float* w_hh_0 = (const float*)d_in[4];
    const float* b_ih_0 = (const float*)d_in[5];
    const float* b_hh_0 = (const float*)d_in[6];
    const float* w_ih_1 = (const float*)d_in[7];
    const float* w_hh_1 = (const float*)d_in[8];
    const float* b_ih_1 = (const float*)d_in[9];
    const float* b_hh_1 = (const float*)d_in[10];
    (void)in_sizes; (void)n_in; (void)out_size;

    float* out = (float*)d_out;
    float* res = out;                                  // [65536, 512]
    float* lh  = out + (size_t)MROWS * HHH;            // [2, 64, 512]
    float* lc  = lh + 2 * BB * HHH;                    // [2, 64, 512]

    cudaFuncSetAttribute(lstm_mma_kernel,
                         cudaFuncAttributeMaxDynamicSharedMemorySize, SMEMT);

    // precision pre-pass (x + both weight matrices in one launch)
    const int n4x = MROWS * IIK / 4;                   // 8388608
    const int n4w = G4 * IIK / 4;                      // 262144
    cvt_all<<<(n4x + 255) / 256, 256>>>(x, w_ih_0, w_ih_1, n4x, n4w);

    // hh precompute (tiled GEMM, both layers in one launch)
    dim3 hgrid(G4 / 64, 2);
    hh_kernel<<<hgrid, 256>>>(h0, w_hh_0, w_hh_1, b_ih_0, b_hh_0, b_ih_1, b_hh_1);

    // HMMA layers
    dim3 ggrid(HHH / TNH, MROWS / TM);   // (16, 512)
    lstm_mma_kernel<<<ggrid, 256, SMEMT>>>(c0, res, lh, lc, 0);
    lstm_mma_kernel<<<ggrid, 256, SMEMT>>>(c0, res, lh, lc, 1);
}

// round 16
// speedup vs baseline: 1.0816x; 1.0099x over previous
#include <cuda_runtime.h>
#include <cuda_fp16.h>
#include <cstdint>

// ---------------- problem dims ----------------
#define MROWS 65536     // T*B
#define IIK   512       // K
#define G4    2048      // 4*H
#define BB    64        // batch
#define HHH   512       // H

// ---------------- tiling ----------------
#define TM   128        // M rows per CTA
#define TNH  32         // hy cols per CTA -> 128 gate cols
#define KC   32         // K chunk
#define NIT  16         // 512/32
#define NPAIR 8
#define NSTAGE 5

// stage: A (128 rows x 80B) + B (128 rows x 80B)
#define ROWSTR 80
#define A_BYTES (128 * ROWSTR)        // 10240
#define B_OFF   A_BYTES
#define STG     (2 * A_BYTES)         // 20480
#define SMEMT   (NSTAGE * STG)        // 102400; epilogue reuses 128x132 f32 (67584)

// ---------------- device scratch (no runtime alloc) ----------------
__device__ __align__(16) __half g_A0[(size_t)MROWS * IIK];
__device__ __align__(16) __half g_A1[(size_t)MROWS * IIK];
__device__ __align__(16) __half g_W[2][G4 * IIK];
__device__ float g_hh[2][BB][G4];

// ---------------- asm helpers (plain sm_80/90 PTX only) ----------------
__device__ __forceinline__ uint32_t smem_to_u32(const void* p) {
    uint32_t a;
    asm("{ .reg .u64 t; cvta.to.shared.u64 t, %1; cvt.u32.u64 %0, t; }"
        : "=r"(a) : "l"(p));
    return a;
}
#define CP_ASYNC16(s, g) \
    asm volatile("cp.async.cg.shared.global [%0], [%1], 16;" :: "r"(s), "l"(g))
#define CP_COMMIT() asm volatile("cp.async.commit_group;" ::: "memory")
#define CP_WAIT1()  asm volatile("cp.async.wait_group 1;" ::: "memory")
#define CP_WAIT0()  asm volatile("cp.async.wait_group 0;" ::: "memory")

#define LDSM4(r, addr) \
    asm volatile("ldmatrix.sync.aligned.m8n8.x4.shared.b16 {%0,%1,%2,%3}, [%4];" \
        : "=r"((r)[0]), "=r"((r)[1]), "=r"((r)[2]), "=r"((r)[3]) : "r"(addr))

__device__ __forceinline__ void mma_f16(float* c, const unsigned* a, const unsigned* b) {
    asm volatile(
        "mma.sync.aligned.m16n8k16.row.col.f32.f16.f16.f32 "
        "{%0,%1,%2,%3}, {%4,%5,%6,%7}, {%8,%9}, {%0,%1,%2,%3};"
        : "+f"(c[0]), "+f"(c[1]), "+f"(c[2]), "+f"(c[3])
        : "r"(a[0]), "r"(a[1]), "r"(a[2]), "r"(a[3]), "r"(b[0]), "r"(b[1]));
}

// ---------------- activations (tanh.approx: 1 MUFU each) ----------------
__device__ __forceinline__ float tanh_ap(float x) {
    float r;
    asm("tanh.approx.f32 %0, %1;" : "=f"(r) : "f"(x));
    return r;
}
__device__ __forceinline__ float sigf(float x) {
    return fmaf(tanh_ap(0.5f * x), 0.5f, 0.5f);
}

// ---------------------------------------------------------------------------
// Merged prep kernel: blocks 0..63 compute the hh GEMM (overlapped under the
// conversion traffic); blocks 64.. convert x and the two weight matrices.
//   hh[l][b][g] = h0[l][b] . w_hh[g] + b_ih[g] + b_hh[g]
// ---------------------------------------------------------------------------
#define HH_BLOCKS 64     // 32 g-tiles x 2 layers
__global__ void __launch_bounds__(256)
prep_kernel(const float* __restrict__ x,
            const float* __restrict__ w_ih_0, const float* __restrict__ w_ih_1,
            const float* __restrict__ h0,
            const float* __restrict__ w_hh_0, const float* __restrict__ w_hh_1,
            const float* __restrict__ b_ih_0, const float* __restrict__ b_hh_0,
            const float* __restrict__ b_ih_1, const float* __restrict__ b_hh_1,
            int n4x, int n4w) {
    __shared__ __align__(16) float As[32][68];
    __shared__ __align__(16) float Bs[32][68];
    const int tid = threadIdx.x;

    if (blockIdx.x >= HH_BLOCKS) {
        // ---------------- converter part ----------------
        const int i = (blockIdx.x - HH_BLOCKS) * 256 + tid;
        if (i < n4x) {
            float4 v = ((const float4*)x)[i];
            ((__half2*)g_A0)[2*i]   = __half2(__float2half(v.x), __float2half(v.y));
            ((__half2*)g_A0)[2*i+1] = __half2(__float2half(v.z), __float2half(v.w));
        }
        if (i < n4w) {
            float4 a = ((const float4*)w_ih_0)[i];
            float4 b = ((const float4*)w_ih_1)[i];
            ((__half2*)g_W[0])[2*i]   = __half2(__float2half(a.x), __float2half(a.y));
            ((__half2*)g_W[0])[2*i+1] = __half2(__float2half(a.z), __float2half(a.w));
            ((__half2*)g_W[1])[2*i]   = __half2(__float2half(b.x), __float2half(b.y));
            ((__half2*)g_W[1])[2*i+1] = __half2(__float2half(b.z), __float2half(b.w));
        }
        return;
    }

    // ---------------- hh GEMM part (64x64 tile, fp32) ----------------
    const int layer = blockIdx.x & 1;
    const int g0 = (blockIdx.x >> 1) * 64;
    const float* __restrict__ w  = layer ? w_hh_1 : w_hh_0;
    const float* __restrict__ bi = layer ? b_ih_1 : b_ih_0;
    const float* __restrict__ bh = layer ? b_hh_1 : b_hh_0;

    const int tx = tid & 15;
    const int ty = tid >> 4;
    const int lr  = tid >> 3;
    const int lk4 = tid & 7;

    float acc[4][4];
#pragma unroll
    for (int i = 0; i < 4; i++)
#pragma unroll
        for (int j = 0; j < 4; j++) acc[i][j] = 0.0f;

    for (int k0 = 0; k0 < IIK; k0 += 32) {
#pragma unroll
        for (int rep = 0; rep < 2; ++rep) {
            const int row = lr + rep * 32;
            float4 av = *(const float4*)(h0 + ((size_t)layer * BB + row) * IIK + k0 + lk4 * 4);
            As[lk4 * 4 + 0][row] = av.x;
            As[lk4 * 4 + 1][row] = av.y;
            As[lk4 * 4 + 2][row] = av.z;
            As[lk4 * 4 + 3][row] = av.w;
            float4 bv = *(const float4*)(w + (size_t)(g0 + row) * IIK + k0 + lk4 * 4);
            Bs[lk4 * 4 + 0][row] = bv.x;
            Bs[lk4 * 4 + 1][row] = bv.y;
            Bs[lk4 * 4 + 2][row] = bv.z;
            Bs[lk4 * 4 + 3][row] = bv.w;
        }
        __syncthreads();
#pragma unroll
        for (int k = 0; k < 32; ++k) {
            float a_[4], b_[4];
#pragma unroll
            for (int i = 0; i < 4; i++) a_[i] = As[k][ty * 4 + i];
#pragma unroll
            for (int j = 0; j < 4; j++) b_[j] = Bs[k][tx * 4 + j];
#pragma unroll
            for (int i = 0; i < 4; i++)
#pragma unroll
                for (int j = 0; j < 4; j++) acc[i][j] = fmaf(a_[i], b_[j], acc[i][j]);
        }
        __syncthreads();
    }
#pragma unroll
    for (int i = 0; i < 4; i++) {
        const int b = ty * 4 + i;
#pragma unroll
        for (int j = 0; j < 4; j++) {
            const int g = g0 + tx * 4 + j;
            g_hh[layer][b][g] = acc[i][j] + bi[g] + bh[g];
        }
    }
}

// ---------------------------------------------------------------------------
// Main HMMA LSTM layer kernel.  grid (16, 512), 256 threads, 2 CTAs/SM.
// Warp tile 32x64; KC=32; 5-stage cp.async; ONE sync + ONE wait per 2 chunks.
// (Exact R14-winning structure — unchanged.)
// Gate-interleaved B rows: smem B row n <-> w_ih row (n%4)*512 + n0h + n/4.
// ---------------------------------------------------------------------------
__global__ void __launch_bounds__(256, 2)
lstm_mma_kernel(const float* __restrict__ c0,
                float* __restrict__ res,
                float* __restrict__ lh,
                float* __restrict__ lc,
                int layer) {
    extern __shared__ __align__(16) char sm[];
    const uint32_t smem_u32 = smem_to_u32(sm);
    const int tid  = threadIdx.x;
    const int wid  = tid >> 5;
    const int lane = tid & 31;
    const int n0h  = blockIdx.x * TNH;
    const int m0   = blockIdx.y * TM;

    const __half* __restrict__ Ax = layer ? g_A1 : g_A0;
    const __half* __restrict__ Wp = g_W[layer];
    const float* __restrict__ hh_l = &g_hh[layer][0][0];
    const float* __restrict__ c0_l = c0 + (size_t)layer * BB * HHH;
    float* __restrict__ lasth = lh + (size_t)layer * BB * HHH;
    float* __restrict__ lastc = lc + (size_t)layer * BB * HHH;

    // ---- loader: per-thread running pointers (4 cp.async per stage) ----
    const int lrow = tid >> 2;           // 0..63 (rows lrow and lrow+64)
    const int lgc  = tid & 3;            // 16B granule along k
    const __half* pA0 = Ax + (size_t)(m0 + lrow) * IIK + lgc * 8;
    const __half* pA1 = pA0 + (size_t)64 * IIK;
    const int wrow0 = (lrow & 3) * 512 + n0h + (lrow >> 2);
    const int wrow1 = ((lrow + 64) & 3) * 512 + n0h + ((lrow + 64) >> 2);
    const __half* pB0 = Wp + (size_t)wrow0 * IIK + lgc * 8;
    const __half* pB1 = Wp + (size_t)wrow1 * IIK + lgc * 8;
    const uint32_t aoff0 = lrow * ROWSTR + lgc * 16;
    const uint32_t aoff1 = aoff0 + 64 * ROWSTR;
    int lstage = 0;

#define LOAD_STAGE()                                                           \
    do {                                                                       \
        const uint32_t _sb = smem_u32 + lstage * STG;                          \
        CP_ASYNC16(_sb + aoff0,         pA0);                                  \
        CP_ASYNC16(_sb + aoff1,         pA1);                                  \
        CP_ASYNC16(_sb + B_OFF + aoff0, pB0);                                  \
        CP_ASYNC16(_sb + B_OFF + aoff1, pB1);                                  \
        CP_COMMIT();                                                           \
        pA0 += KC; pA1 += KC; pB0 += KC; pB1 += KC;                            \
        lstage = (lstage + 1 == NSTAGE) ? 0 : lstage + 1;                      \
    } while (0)

    // ---- ldmatrix invariants: warp grid 4 (wm, 32 rows) x 2 (wn, 64 cols) ----
    const int wm = wid & 3;
    const int wn = wid >> 2;
    const uint32_t aBase = (uint32_t)(wm * 32) * ROWSTR
                         + (uint32_t)(lane & 15) * ROWSTR
                         + (uint32_t)((lane >> 4) & 1) * 16;
    const uint32_t bBase = B_OFF + (uint32_t)(wn * 64) * ROWSTR
                         + (uint32_t)(((lane >> 4) & 1) * 8 + (lane & 7)) * ROWSTR
                         + (uint32_t)((lane >> 3) & 1) * 16;

    float acc[2][8][4];
#pragma unroll
    for (int mt = 0; mt < 2; ++mt)
#pragma unroll
        for (int nb = 0; nb < 8; ++nb)
#pragma unroll
            for (int q = 0; q < 4; ++q) acc[mt][nb][q] = 0.0f;

#define COMPUTE_CHUNK(SBASE)                                                   \
    do {                                                                       \
        const uint32_t _cb = (SBASE);                                          \
        _Pragma("unroll")                                                      \
        for (int ks = 0; ks < 2; ++ks) {                                       \
            unsigned ah[2][4];                                                 \
            _Pragma("unroll")                                                  \
            for (int mt = 0; mt < 2; ++mt)                                     \
                LDSM4(ah[mt], _cb + aBase + (uint32_t)(mt * 16) * ROWSTR + ks * 32); \
            unsigned bh[4][4];                                                 \
            _Pragma("unroll")                                                  \
            for (int p = 0; p < 4; ++p)                                        \
                LDSM4(bh[p], _cb + bBase + (uint32_t)(p * 16) * ROWSTR + ks * 32);   \
            _Pragma("unroll")                                                  \
            for (int mt = 0; mt < 2; ++mt)                                     \
                _Pragma("unroll")                                              \
                for (int p = 0; p < 4; ++p) {                                  \
                    mma_f16(acc[mt][2*p],   ah[mt], &bh[p][0]);                \
                    mma_f16(acc[mt][2*p+1], ah[mt], &bh[p][2]);                \
                }                                                              \
        }                                                                      \
    } while (0)

    LOAD_STAGE();   // stage 0
    LOAD_STAGE();   // stage 1
    LOAD_STAGE();   // stage 2

    for (int j = 0; j < NPAIR; ++j) {
        if (j + 1 < NPAIR) CP_WAIT1(); else CP_WAIT0();
        __syncthreads();          // pair barrier: data visibility + stage-reuse guard
        if (2 * j + 3 < NIT) LOAD_STAGE();
        if (2 * j + 4 < NIT) LOAD_STAGE();

        const int s0 = (2 * j) % NSTAGE;
        const int s1 = (2 * j + 1) % NSTAGE;
        COMPUTE_CHUNK(smem_u32 + s0 * STG);
        COMPUTE_CHUNK(smem_u32 + s1 * STG);   // no barrier between the two
    }
    __syncthreads();              // all LDSM done before smem reuse as Gs

    // ---- epilogue: dump gate tile (128 x 128 f32, stride 132) into smem ----
    float* Gs = (float*)sm;
#pragma unroll
    for (int mt = 0; mt < 2; ++mt) {
        const int r0 = wm * 32 + mt * 16 + (lane >> 2);
#pragma unroll
        for (int nb = 0; nb < 8; ++nb) {
            const int cb = wn * 64 + nb * 8 + (lane & 3) * 2;
            Gs[r0 * 132 + cb]           = acc[mt][nb][0];
            Gs[r0 * 132 + cb + 1]       = acc[mt][nb][1];
            Gs[(r0 + 8) * 132 + cb]     = acc[mt][nb][2];
            Gs[(r0 + 8) * 132 + cb + 1] = acc[mt][nb][3];
        }
    }
    __syncthreads();

    // ---- fused LSTM pointwise: 128 rows x 16 col-pairs per CTA ----
    // 4 gates of one hy col contiguous in Gs -> one float4 LDS each.
    for (int e = tid; e < TM * (TNH / 2); e += 256) {
        const int row = e >> 4;
        const int c2  = e & 15;
        const int m   = m0 + row;
        const int b   = m & (BB - 1);
        const int nh  = n0h + c2 * 2;
        const float* hhb = hh_l + (size_t)b * G4;
        float hy2[2], cy2[2];
#pragma unroll
        for (int u = 0; u < 2; ++u) {
            const int col = c2 * 2 + u;
            float4 gv4 = *(const float4*)&Gs[row * 132 + col * 4];
            float ig = gv4.x + hhb[nh + u];
            float fg = gv4.y + hhb[512 + nh + u];
            float gg = gv4.z + hhb[1024 + nh + u];
            float og = gv4.w + hhb[1536 + nh + u];
            float cy = sigf(fg) * c0_l[(size_t)b * HHH + nh + u] + sigf(ig) * tanh_ap(gg);
            cy2[u] = cy;
            hy2[u] = sigf(og) * tanh_ap(cy);
        }
        if (layer == 0) {
            *(__half2*)(g_A1 + (size_t)m * HHH + nh) =
                __half2(__float2half(hy2[0]), __float2half(hy2[1]));
        } else {
            *(float2*)(res + (size_t)m * HHH + nh) = make_float2(hy2[0], hy2[1]);
        }
        if (m >= MROWS - BB) {
            *(float2*)(lasth + (size_t)b * HHH + nh) = make_float2(hy2[0], hy2[1]);
            *(float2*)(lastc + (size_t)b * HHH + nh) = make_float2(cy2[0], cy2[1]);
        }
    }
}

// ---------------------------------------------------------------------------
extern "C" void kernel_launch(void* const* d_in, const int* in_sizes, int n_in,
                              void* d_out, int out_size) {
    const float* x      = (const float*)d_in[0];
    const float* h0     = (const float*)d_in[1];
    const float* c0     = (const float*)d_in[2];
    const float* w_ih_0 = (const float*)d_in[3];
    const float* w_hh_0 = (const float*)d_in[4];
    const float* b_ih_0 = (const float*)d_in[5];
    const float* b_hh_0 = (const float*)d_in[6];
    const float* w_ih_1 = (const float*)d_in[7];
    const float* w_hh_1 = (const float*)d_in[8];
    const float* b_ih_1 = (const float*)d_in[9];
    const float* b_hh_1 = (const float*)d_in[10];
    (void)in_sizes; (void)n_in; (void)out_size;

    float* out = (float*)d_out;
    float* res = out;                                  // [65536, 512]
    float* lh  = out + (size_t)MROWS * HHH;            // [2, 64, 512]
    float* lc  = lh + 2 * BB * HHH;                    // [2, 64, 512]

    cudaFuncSetAttribute(lstm_mma_kernel,
                         cudaFuncAttributeMaxDynamicSharedMemorySize, SMEMT);

    // merged prep: hh GEMM (blocks 0..63) overlapped with fp16 conversion
    const int n4x = MROWS * IIK / 4;                   // 8388608
    const int n4w = G4 * IIK / 4;                      // 262144
    const int cvt_blocks = (n4x + 255) / 256;          // 32768
    prep_kernel<<<HH_BLOCKS + cvt_blocks, 256>>>(
        x, w_ih_0, w_ih_1, h0, w_hh_0, w_hh_1,
        b_ih_0, b_hh_0, b_ih_1, b_hh_1, n4x, n4w);

    // HMMA layers
    dim3 ggrid(HHH / TNH, MROWS / TM);   // (16, 512)
    lstm_mma_kernel<<<ggrid, 256, SMEMT>>>(c0, res, lh, lc, 0);
    lstm_mma_kernel<<<ggrid, 256, SMEMT>>>(c0, res, lh, lc, 1);
}

// round 17
// speedup vs baseline: 1.0943x; 1.0118x over previous
#include <cuda_runtime.h>
#include <cuda_fp16.h>
#include <cstdint>

// ---------------- problem dims ----------------
#define MROWS 65536     // T*B
#define IIK   512       // K
#define G4    2048      // 4*H
#define BB    64        // batch
#define HHH   512       // H

// ---------------- tiling ----------------
#define TM   128        // M rows per CTA
#define TNH  32         // hy cols per CTA -> 128 gate cols
#define KC   32         // K chunk
#define NIT  16         // 512/32
#define NPAIR 8
#define NSTAGE 5

// stage: A (128 rows x 80B) + B (128 rows x 80B)
#define ROWSTR 80
#define A_BYTES (128 * ROWSTR)        // 10240
#define B_OFF   A_BYTES
#define STG     (2 * A_BYTES)         // 20480
#define SMEMT   (NSTAGE * STG)        // 102400; epilogue reuses 128x132 f32 (67584)

// ---------------- device scratch (no runtime alloc) ----------------
__device__ __align__(16) __half g_A0[(size_t)MROWS * IIK];
__device__ __align__(16) __half g_A1[(size_t)MROWS * IIK];
__device__ __align__(16) __half g_W[2][G4 * IIK];
__device__ float g_hh[2][BB][G4];

// ---------------- asm helpers (plain sm_80/90 PTX only) ----------------
__device__ __forceinline__ uint32_t smem_to_u32(const void* p) {
    uint32_t a;
    asm("{ .reg .u64 t; cvta.to.shared.u64 t, %1; cvt.u32.u64 %0, t; }"
        : "=r"(a) : "l"(p));
    return a;
}
#define CP_ASYNC16(s, g) \
    asm volatile("cp.async.cg.shared.global [%0], [%1], 16;" :: "r"(s), "l"(g))
#define CP_COMMIT() asm volatile("cp.async.commit_group;" ::: "memory")
#define CP_WAIT1()  asm volatile("cp.async.wait_group 1;" ::: "memory")
#define CP_WAIT0()  asm volatile("cp.async.wait_group 0;" ::: "memory")

#define LDSM4(r, addr) \
    asm volatile("ldmatrix.sync.aligned.m8n8.x4.shared.b16 {%0,%1,%2,%3}, [%4];" \
        : "=r"((r)[0]), "=r"((r)[1]), "=r"((r)[2]), "=r"((r)[3]) : "r"(addr))

__device__ __forceinline__ void mma_f16(float* c, const unsigned* a, const unsigned* b) {
    asm volatile(
        "mma.sync.aligned.m16n8k16.row.col.f32.f16.f16.f32 "
        "{%0,%1,%2,%3}, {%4,%5,%6,%7}, {%8,%9}, {%0,%1,%2,%3};"
        : "+f"(c[0]), "+f"(c[1]), "+f"(c[2]), "+f"(c[3])
        : "r"(a[0]), "r"(a[1]), "r"(a[2]), "r"(a[3]), "r"(b[0]), "r"(b[1]));
}

// ---------------- activations (tanh.approx: 1 MUFU each) ----------------
__device__ __forceinline__ float tanh_ap(float x) {
    float r;
    asm("tanh.approx.f32 %0, %1;" : "=f"(r) : "f"(x));
    return r;
}
__device__ __forceinline__ float sigf(float x) {
    return fmaf(tanh_ap(0.5f * x), 0.5f, 0.5f);
}

// ---------------------------------------------------------------------------
// Merged prep kernel: blocks 0..63 compute the hh GEMM (overlapped under the
// conversion traffic); blocks 64.. convert x (4 float4 per thread, MLP=4)
// and the two weight matrices.
//   hh[l][b][g] = h0[l][b] . w_hh[g] + b_ih[g] + b_hh[g]
// ---------------------------------------------------------------------------
#define HH_BLOCKS 64     // 32 g-tiles x 2 layers
#define CVT_V 4          // float4s per converter thread
__global__ void __launch_bounds__(256)
prep_kernel(const float* __restrict__ x,
            const float* __restrict__ w_ih_0, const float* __restrict__ w_ih_1,
            const float* __restrict__ h0,
            const float* __restrict__ w_hh_0, const float* __restrict__ w_hh_1,
            const float* __restrict__ b_ih_0, const float* __restrict__ b_hh_0,
            const float* __restrict__ b_ih_1, const float* __restrict__ b_hh_1,
            int n4x, int n4w) {
    __shared__ __align__(16) float As[32][68];
    __shared__ __align__(16) float Bs[32][68];
    const int tid = threadIdx.x;

    if (blockIdx.x >= HH_BLOCKS) {
        // ---------------- converter part ----------------
        const int cb = blockIdx.x - HH_BLOCKS;
        // x: each thread converts CVT_V consecutive float4s, loads batched (MLP=4)
        {
            const int i0 = (cb * 256 + tid) * CVT_V;
            if (i0 + CVT_V <= n4x) {
                float4 v[CVT_V];
#pragma unroll
                for (int u = 0; u < CVT_V; ++u)
                    v[u] = __ldcs(&((const float4*)x)[i0 + u]);   // streaming read
#pragma unroll
                for (int u = 0; u < CVT_V; ++u) {
                    const int i = i0 + u;
                    ((__half2*)g_A0)[2*i]   = __half2(__float2half(v[u].x), __float2half(v[u].y));
                    ((__half2*)g_A0)[2*i+1] = __half2(__float2half(v[u].z), __float2half(v[u].w));
                }
            }
        }
        // weights: first n4w/256 blocks also convert one float4 of each W
        const int i = cb * 256 + tid;
        if (i < n4w) {
            float4 a = ((const float4*)w_ih_0)[i];
            float4 b = ((const float4*)w_ih_1)[i];
            ((__half2*)g_W[0])[2*i]   = __half2(__float2half(a.x), __float2half(a.y));
            ((__half2*)g_W[0])[2*i+1] = __half2(__float2half(a.z), __float2half(a.w));
            ((__half2*)g_W[1])[2*i]   = __half2(__float2half(b.x), __float2half(b.y));
            ((__half2*)g_W[1])[2*i+1] = __half2(__float2half(b.z), __float2half(b.w));
        }
        return;
    }

    // ---------------- hh GEMM part (64x64 tile, fp32) ----------------
    const int layer = blockIdx.x & 1;
    const int g0 = (blockIdx.x >> 1) * 64;
    const float* __restrict__ w  = layer ? w_hh_1 : w_hh_0;
    const float* __restrict__ bi = layer ? b_ih_1 : b_ih_0;
    const float* __restrict__ bh = layer ? b_hh_1 : b_hh_0;

    const int tx = tid & 15;
    const int ty = tid >> 4;
    const int lr  = tid >> 3;
    const int lk4 = tid & 7;

    float acc[4][4];
#pragma unroll
    for (int i = 0; i < 4; i++)
#pragma unroll
        for (int j = 0; j < 4; j++) acc[i][j] = 0.0f;

    for (int k0 = 0; k0 < IIK; k0 += 32) {
#pragma unroll
        for (int rep = 0; rep < 2; ++rep) {
            const int row = lr + rep * 32;
            float4 av = *(const float4*)(h0 + ((size_t)layer * BB + row) * IIK + k0 + lk4 * 4);
            As[lk4 * 4 + 0][row] = av.x;
            As[lk4 * 4 + 1][row] = av.y;
            As[lk4 * 4 + 2][row] = av.z;
            As[lk4 * 4 + 3][row] = av.w;
            float4 bv = *(const float4*)(w + (size_t)(g0 + row) * IIK + k0 + lk4 * 4);
            Bs[lk4 * 4 + 0][row] = bv.x;
            Bs[lk4 * 4 + 1][row] = bv.y;
            Bs[lk4 * 4 + 2][row] = bv.z;
            Bs[lk4 * 4 + 3][row] = bv.w;
        }
        __syncthreads();
#pragma unroll
        for (int k = 0; k < 32; ++k) {
            float a_[4], b_[4];
#pragma unroll
            for (int i = 0; i < 4; i++) a_[i] = As[k][ty * 4 + i];
#pragma unroll
            for (int j = 0; j < 4; j++) b_[j] = Bs[k][tx * 4 + j];
#pragma unroll
            for (int i = 0; i < 4; i++)
#pragma unroll
                for (int j = 0; j < 4; j++) acc[i][j] = fmaf(a_[i], b_[j], acc[i][j]);
        }
        __syncthreads();
    }
#pragma unroll
    for (int i = 0; i < 4; i++) {
        const int b = ty * 4 + i;
#pragma unroll
        for (int j = 0; j < 4; j++) {
            const int g = g0 + tx * 4 + j;
            g_hh[layer][b][g] = acc[i][j] + bi[g] + bh[g];
        }
    }
}

// ---------------------------------------------------------------------------
// Main HMMA LSTM layer kernel.  grid (16, 512), 256 threads, 2 CTAs/SM.
// Warp tile 32x64; KC=32; 5-stage cp.async; ONE sync + ONE wait per 2 chunks.
// (Exact R14/R15-winning structure — unchanged.)
// Gate-interleaved B rows: smem B row n <-> w_ih row (n%4)*512 + n0h + n/4.
// ---------------------------------------------------------------------------
__global__ void __launch_bounds__(256, 2)
lstm_mma_kernel(const float* __restrict__ c0,
                float* __restrict__ res,
                float* __restrict__ lh,
                float* __restrict__ lc,
                int layer) {
    extern __shared__ __align__(16) char sm[];
    const uint32_t smem_u32 = smem_to_u32(sm);
    const int tid  = threadIdx.x;
    const int wid  = tid >> 5;
    const int lane = tid & 31;
    const int n0h  = blockIdx.x * TNH;
    const int m0   = blockIdx.y * TM;

    const __half* __restrict__ Ax = layer ? g_A1 : g_A0;
    const __half* __restrict__ Wp = g_W[layer];
    const float* __restrict__ hh_l = &g_hh[layer][0][0];
    const float* __restrict__ c0_l = c0 + (size_t)layer * BB * HHH;
    float* __restrict__ lasth = lh + (size_t)layer * BB * HHH;
    float* __restrict__ lastc = lc + (size_t)layer * BB * HHH;

    // ---- loader: per-thread running pointers (4 cp.async per stage) ----
    const int lrow = tid >> 2;           // 0..63 (rows lrow and lrow+64)
    const int lgc  = tid & 3;            // 16B granule along k
    const __half* pA0 = Ax + (size_t)(m0 + lrow) * IIK + lgc * 8;
    const __half* pA1 = pA0 + (size_t)64 * IIK;
    const int wrow0 = (lrow & 3) * 512 + n0h + (lrow >> 2);
    const int wrow1 = ((lrow + 64) & 3) * 512 + n0h + ((lrow + 64) >> 2);
    const __half* pB0 = Wp + (size_t)wrow0 * IIK + lgc * 8;
    const __half* pB1 = Wp + (size_t)wrow1 * IIK + lgc * 8;
    const uint32_t aoff0 = lrow * ROWSTR + lgc * 16;
    const uint32_t aoff1 = aoff0 + 64 * ROWSTR;
    int lstage = 0;

#define LOAD_STAGE()                                                           \
    do {                                                                       \
        const uint32_t _sb = smem_u32 + lstage * STG;                          \
        CP_ASYNC16(_sb + aoff0,         pA0);                                  \
        CP_ASYNC16(_sb + aoff1,         pA1);                                  \
        CP_ASYNC16(_sb + B_OFF + aoff0, pB0);                                  \
        CP_ASYNC16(_sb + B_OFF + aoff1, pB1);                                  \
        CP_COMMIT();                                                           \
        pA0 += KC; pA1 += KC; pB0 += KC; pB1 += KC;                            \
        lstage = (lstage + 1 == NSTAGE) ? 0 : lstage + 1;                      \
    } while (0)

    // ---- ldmatrix invariants: warp grid 4 (wm, 32 rows) x 2 (wn, 64 cols) ----
    const int wm = wid & 3;
    const int wn = wid >> 2;
    const uint32_t aBase = (uint32_t)(wm * 32) * ROWSTR
                         + (uint32_t)(lane & 15) * ROWSTR
                         + (uint32_t)((lane >> 4) & 1) * 16;
    const uint32_t bBase = B_OFF + (uint32_t)(wn * 64) * ROWSTR
                         + (uint32_t)(((lane >> 4) & 1) * 8 + (lane & 7)) * ROWSTR
                         + (uint32_t)((lane >> 3) & 1) * 16;

    float acc[2][8][4];
#pragma unroll
    for (int mt = 0; mt < 2; ++mt)
#pragma unroll
        for (int nb = 0; nb < 8; ++nb)
#pragma unroll
            for (int q = 0; q < 4; ++q) acc[mt][nb][q] = 0.0f;

#define COMPUTE_CHUNK(SBASE)                                                   \
    do {                                                                       \
        const uint32_t _cb = (SBASE);                                          \
        _Pragma("unroll")                                                      \
        for (int ks = 0; ks < 2; ++ks) {                                       \
            unsigned ah[2][4];                                                 \
            _Pragma("unroll")                                                  \
            for (int mt = 0; mt < 2; ++mt)                                     \
                LDSM4(ah[mt], _cb + aBase + (uint32_t)(mt * 16) * ROWSTR + ks * 32); \
            unsigned bh[4][4];                                                 \
            _Pragma("unroll")                                                  \
            for (int p = 0; p < 4; ++p)                                        \
                LDSM4(bh[p], _cb + bBase + (uint32_t)(p * 16) * ROWSTR + ks * 32);   \
            _Pragma("unroll")                                                  \
            for (int mt = 0; mt < 2; ++mt)                                     \
                _Pragma("unroll")                                              \
                for (int p = 0; p < 4; ++p) {                                  \
                    mma_f16(acc[mt][2*p],   ah[mt], &bh[p][0]);                \
                    mma_f16(acc[mt][2*p+1], ah[mt], &bh[p][2]);                \
                }                                                              \
        }                                                                      \
    } while (0)

    LOAD_STAGE();   // stage 0
    LOAD_STAGE();   // stage 1
    LOAD_STAGE();   // stage 2

    for (int j = 0; j < NPAIR; ++j) {
        if (j + 1 < NPAIR) CP_WAIT1(); else CP_WAIT0();
        __syncthreads();          // pair barrier: data visibility + stage-reuse guard
        if (2 * j + 3 < NIT) LOAD_STAGE();
        if (2 * j + 4 < NIT) LOAD_STAGE();

        const int s0 = (2 * j) % NSTAGE;
        const int s1 = (2 * j + 1) % NSTAGE;
        COMPUTE_CHUNK(smem_u32 + s0 * STG);
        COMPUTE_CHUNK(smem_u32 + s1 * STG);   // no barrier between the two
    }
    __syncthreads();              // all LDSM done before smem reuse as Gs

    // ---- epilogue: dump gate tile (128 x 128 f32, stride 132) into smem ----
    float* Gs = (float*)sm;
#pragma unroll
    for (int mt = 0; mt < 2; ++mt) {
        const int r0 = wm * 32 + mt * 16 + (lane >> 2);
#pragma unroll
        for (int nb = 0; nb < 8; ++nb) {
            const int cb = wn * 64 + nb * 8 + (lane & 3) * 2;
            Gs[r0 * 132 + cb]           = acc[mt][nb][0];
            Gs[r0 * 132 + cb + 1]       = acc[mt][nb][1];
            Gs[(r0 + 8) * 132 + cb]     = acc[mt][nb][2];
            Gs[(r0 + 8) * 132 + cb + 1] = acc[mt][nb][3];
        }
    }
    __syncthreads();

    // ---- fused LSTM pointwise: 128 rows x 16 col-pairs per CTA ----
    // 4 gates of one hy col contiguous in Gs -> one float4 LDS each.
    for (int e = tid; e < TM * (TNH / 2); e += 256) {
        const int row = e >> 4;
        const int c2  = e & 15;
        const int m   = m0 + row;
        const int b   = m & (BB - 1);
        const int nh  = n0h + c2 * 2;
        const float* hhb = hh_l + (size_t)b * G4;
        float hy2[2], cy2[2];
#pragma unroll
        for (int u = 0; u < 2; ++u) {
            const int col = c2 * 2 + u;
            float4 gv4 = *(const float4*)&Gs[row * 132 + col * 4];
            float ig = gv4.x + hhb[nh + u];
            float fg = gv4.y + hhb[512 + nh + u];
            float gg = gv4.z + hhb[1024 + nh + u];
            float og = gv4.w + hhb[1536 + nh + u];
            float cy = sigf(fg) * c0_l[(size_t)b * HHH + nh + u] + sigf(ig) * tanh_ap(gg);
            cy2[u] = cy;
            hy2[u] = sigf(og) * tanh_ap(cy);
        }
        if (layer == 0) {
            *(__half2*)(g_A1 + (size_t)m * HHH + nh) =
                __half2(__float2half(hy2[0]), __float2half(hy2[1]));
        } else {
            *(float2*)(res + (size_t)m * HHH + nh) = make_float2(hy2[0], hy2[1]);
        }
        if (m >= MROWS - BB) {
            *(float2*)(lasth + (size_t)b * HHH + nh) = make_float2(hy2[0], hy2[1]);
            *(float2*)(lastc + (size_t)b * HHH + nh) = make_float2(cy2[0], cy2[1]);
        }
    }
}

// ---------------------------------------------------------------------------
extern "C" void kernel_launch(void* const* d_in, const int* in_sizes, int n_in,
                              void* d_out, int out_size) {
    const float* x      = (const float*)d_in[0];
    const float* h0     = (const float*)d_in[1];
    const float* c0     = (const float*)d_in[2];
    const float* w_ih_0 = (const float*)d_in[3];
    const float* w_hh_0 = (const float*)d_in[4];
    const float* b_ih_0 = (const float*)d_in[5];
    const float* b_hh_0 = (const float*)d_in[6];
    const float* w_ih_1 = (const float*)d_in[7];
    const float* w_hh_1 = (const float*)d_in[8];
    const float* b_ih_1 = (const float*)d_in[9];
    const float* b_hh_1 = (const float*)d_in[10];
    (void)in_sizes; (void)n_in; (void)out_size;

    float* out = (float*)d_out;
    float* res = out;                                  // [65536, 512]
    float* lh  = out + (size_t)MROWS * HHH;            // [2, 64, 512]
    float* lc  = lh + 2 * BB * HHH;                    // [2, 64, 512]

    cudaFuncSetAttribute(lstm_mma_kernel,
                         cudaFuncAttributeMaxDynamicSharedMemorySize, SMEMT);

    // merged prep: hh GEMM (blocks 0..63) overlapped with fp16 conversion
    const int n4x = MROWS * IIK / 4;                   // 8388608 (divisible by CVT_V*256)
    const int n4w = G4 * IIK / 4;                      // 262144
    const int cvt_blocks = (n4x + 256 * CVT_V - 1) / (256 * CVT_V);   // 8192
    prep_kernel<<<HH_BLOCKS + cvt_blocks, 256>>>(
        x, w_ih_0, w_ih_1, h0, w_hh_0, w_hh_1,
        b_ih_0, b_hh_0, b_ih_1, b_hh_1, n4x, n4w);

    // HMMA layers
    dim3 ggrid(HHH / TNH, MROWS / TM);   // (16, 512)
    lstm_mma_kernel<<<ggrid, 256, SMEMT>>>(c0, res, lh, lc, 0);
    lstm_mma_kernel<<<ggrid, 256, SMEMT>>>(c0, res, lh, lc, 1);
}